// round 1
// baseline (speedup 1.0000x reference)
#include <cuda_runtime.h>
#include <cuda_bf16.h>
#include <cstdint>

// Problem constants
#define B_  64
#define C_  3
#define H_  224
#define W_  224
#define GH  28
#define GW  28
#define D_  768
#define KD  192                 // C*8*8
#define M_  (B_*GH*GW)          // 50176

// ---- scratch (no cudaMalloc allowed) ----
__device__ unsigned int g_absmax_bits[2];                 // [0]=x, [1]=w
__device__ __nv_bfloat16 g_xq[(size_t)M_ * KD];           // 19.3 MB
__device__ __nv_bfloat16 g_wq[(size_t)D_ * KD];           // 288 KB

// ---------------------------------------------------------------------------
__global__ void zero_absmax_kernel() {
    g_absmax_bits[0] = 0u;
    g_absmax_bits[1] = 0u;
}

__global__ void absmax_kernel(const float4* __restrict__ p, int n4, int slot) {
    float m = 0.f;
    for (int i = blockIdx.x * blockDim.x + threadIdx.x; i < n4;
         i += gridDim.x * blockDim.x) {
        float4 v = p[i];
        m = fmaxf(m, fmaxf(fmaxf(fabsf(v.x), fabsf(v.y)),
                           fmaxf(fabsf(v.z), fabsf(v.w))));
    }
#pragma unroll
    for (int o = 16; o > 0; o >>= 1)
        m = fmaxf(m, __shfl_xor_sync(0xffffffffu, m, o));
    if ((threadIdx.x & 31) == 0)
        atomicMax(&g_absmax_bits[slot], __float_as_uint(m));
}

// quantize one float -> integer-valued float (round half-to-even like jnp.round)
__device__ __forceinline__ float fq(float v, float s) {
    return rintf(fminf(fmaxf(v / s, -127.f), 127.f));
}

__device__ __forceinline__ unsigned int pack2(float a, float b, float s) {
    __nv_bfloat162 h = __floats2bfloat162_rn(fq(a, s), fq(b, s));
    return *reinterpret_cast<unsigned int*>(&h);
}

// w is [D, C, 8, 8] = [768, 192] row-major already; straight quantize-copy.
__global__ void quant_w_kernel(const float* __restrict__ w) {
    float s = fmaxf(__uint_as_float(g_absmax_bits[1]), 1e-8f) / 127.0f;
    int i = blockIdx.x * blockDim.x + threadIdx.x;          // per 4 elems
    int n4 = (D_ * KD) / 4;
    if (i >= n4) return;
    float4 v = reinterpret_cast<const float4*>(w)[i];
    uint2 o;
    o.x = pack2(v.x, v.y, s);
    o.y = pack2(v.z, v.w, s);
    reinterpret_cast<uint2*>(g_wq)[i] = o;
}

// x: [B, C, 224, 224] -> g_xq: [m = b*784 + xb*28 + yb][k = c*64 + p*8 + q]
// one thread per 8-element run (one patch row): fully coalesced reads.
__global__ void quant_x_kernel(const float* __restrict__ x) {
    float s = fmaxf(__uint_as_float(g_absmax_bits[0]), 1e-8f) / 127.0f;
    int tid = blockIdx.x * blockDim.x + threadIdx.x;
    const int total = B_ * C_ * H_ * GW;                    // 1,204,224 runs
    if (tid >= total) return;
    int wb = tid % GW;
    int h  = (tid / GW) % H_;
    int c  = (tid / (GW * H_)) % C_;
    int b  = tid / (GW * H_ * C_);
    const float4* src = reinterpret_cast<const float4*>(
        x + ((((size_t)b * C_ + c) * H_ + h) * W_ + (size_t)wb * 8));
    float4 v0 = src[0], v1 = src[1];
    int xb = h >> 3, p = h & 7;
    size_t m = (size_t)b * (GH * GW) + (size_t)xb * GW + wb;
    size_t k = (size_t)c * 64 + (size_t)p * 8;
    uint4 o;
    o.x = pack2(v0.x, v0.y, s);
    o.y = pack2(v0.z, v0.w, s);
    o.z = pack2(v1.x, v1.y, s);
    o.w = pack2(v1.z, v1.w, s);
    *reinterpret_cast<uint4*>(g_xq + m * KD + k) = o;
}

// ---------------------------------------------------------------------------
// GEMM: out[M,768] = (xq[M,192] @ wq[768,192]^T) * (s_x*s_w) + bias
// Block tile 128x128, full K=192 staged in smem, mma.sync m16n8k16 bf16.
// smem stride 200 bf16 (=100 words): rows land 4 banks apart -> conflict-free
// fragment loads.
#define ASTRIDE 200
#define GEMM_SMEM (2 * 128 * ASTRIDE * 2)

__global__ void __launch_bounds__(256)
gemm_kernel(const float* __restrict__ bias, float* __restrict__ out) {
    extern __shared__ __nv_bfloat16 smem[];
    __nv_bfloat16* As = smem;                 // [128][200]
    __nv_bfloat16* Bs = smem + 128 * ASTRIDE; // [128][200]

    const int bn = blockIdx.x;  // 0..5   (N blocks of 128)
    const int bm = blockIdx.y;  // 0..391 (M blocks of 128)
    const int tid = threadIdx.x;

    float sx = fmaxf(__uint_as_float(g_absmax_bits[0]), 1e-8f) / 127.0f;
    float sw = fmaxf(__uint_as_float(g_absmax_bits[1]), 1e-8f) / 127.0f;
    float s = sx * sw;

    // stage A and B tiles (24 uint4 per 192-elem row, 128 rows each)
    const uint4* gA = reinterpret_cast<const uint4*>(g_xq + (size_t)bm * 128 * KD);
    const uint4* gB = reinterpret_cast<const uint4*>(g_wq + (size_t)bn * 128 * KD);
#pragma unroll
    for (int it = 0; it < 12; it++) {
        int cid = tid + it * 256;
        int row = cid / 24, cc = cid % 24;
        *reinterpret_cast<uint4*>(&As[row * ASTRIDE + cc * 8]) = gA[row * 24 + cc];
        *reinterpret_cast<uint4*>(&Bs[row * ASTRIDE + cc * 8]) = gB[row * 24 + cc];
    }
    __syncthreads();

    const int warp = tid >> 5, lane = tid & 31;
    const int wm = warp & 3;   // 4 warps over M (32 rows each)
    const int wn = warp >> 2;  // 2 warps over N (64 cols each)
    const int g = lane >> 2, t = lane & 3;

    float acc[2][8][4];
#pragma unroll
    for (int i = 0; i < 2; i++)
#pragma unroll
        for (int j = 0; j < 8; j++)
#pragma unroll
            for (int r = 0; r < 4; r++) acc[i][j][r] = 0.f;

    const uint32_t* As32 = reinterpret_cast<const uint32_t*>(As);
    const uint32_t* Bs32 = reinterpret_cast<const uint32_t*>(Bs);

#pragma unroll
    for (int ks = 0; ks < 12; ks++) {
        const int k0w = ks * 8;  // word offset (k0/2)
        uint32_t a[2][4];
#pragma unroll
        for (int i = 0; i < 2; i++) {
            int r0 = wm * 32 + i * 16 + g;
            a[i][0] = As32[r0 * 100 + k0w + t];
            a[i][1] = As32[(r0 + 8) * 100 + k0w + t];
            a[i][2] = As32[r0 * 100 + k0w + t + 4];
            a[i][3] = As32[(r0 + 8) * 100 + k0w + t + 4];
        }
#pragma unroll
        for (int j = 0; j < 8; j++) {
            int n0 = wn * 64 + j * 8 + g;
            uint32_t b0 = Bs32[n0 * 100 + k0w + t];
            uint32_t b1 = Bs32[n0 * 100 + k0w + t + 4];
#pragma unroll
            for (int i = 0; i < 2; i++) {
                asm volatile(
                    "mma.sync.aligned.m16n8k16.row.col.f32.bf16.bf16.f32 "
                    "{%0,%1,%2,%3}, {%4,%5,%6,%7}, {%8,%9}, {%0,%1,%2,%3};\n"
                    : "+f"(acc[i][j][0]), "+f"(acc[i][j][1]),
                      "+f"(acc[i][j][2]), "+f"(acc[i][j][3])
                    : "r"(a[i][0]), "r"(a[i][1]), "r"(a[i][2]), "r"(a[i][3]),
                      "r"(b0), "r"(b1));
            }
        }
    }

    // epilogue: scale + bias, fp32 float2 stores (dims divide evenly, no guards)
    const int m_base = bm * 128 + wm * 32;
    const int n_base = bn * 128 + wn * 64;
#pragma unroll
    for (int i = 0; i < 2; i++) {
        int row0 = m_base + i * 16 + g;
#pragma unroll
        for (int j = 0; j < 8; j++) {
            int col = n_base + j * 8 + t * 2;
            float2 bv = *reinterpret_cast<const float2*>(&bias[col]);
            float2 v0 = make_float2(acc[i][j][0] * s + bv.x,
                                    acc[i][j][1] * s + bv.y);
            float2 v1 = make_float2(acc[i][j][2] * s + bv.x,
                                    acc[i][j][3] * s + bv.y);
            *reinterpret_cast<float2*>(&out[(size_t)row0 * D_ + col]) = v0;
            *reinterpret_cast<float2*>(&out[(size_t)(row0 + 8) * D_ + col]) = v1;
        }
    }
}

// ---------------------------------------------------------------------------
extern "C" void kernel_launch(void* const* d_in, const int* in_sizes, int n_in,
                              void* d_out, int out_size) {
    (void)in_sizes; (void)n_in; (void)out_size;
    const float* x = (const float*)d_in[0];
    const float* w = (const float*)d_in[1];
    const float* b = (const float*)d_in[2];
    float* out = (float*)d_out;

    zero_absmax_kernel<<<1, 1>>>();
    absmax_kernel<<<592, 256>>>((const float4*)x, (B_ * C_ * H_ * W_) / 4, 0);
    absmax_kernel<<<144, 256>>>((const float4*)w, (D_ * KD) / 4, 1);
    quant_w_kernel<<<((D_ * KD) / 4 + 255) / 256, 256>>>(w);
    quant_x_kernel<<<(B_ * C_ * H_ * GW + 255) / 256, 256>>>(x);

    cudaFuncSetAttribute(gemm_kernel,
                         cudaFuncAttributeMaxDynamicSharedMemorySize, GEMM_SMEM);
    dim3 grid(D_ / 128, M_ / 128);  // (6, 392)
    gemm_kernel<<<grid, 256, GEMM_SMEM>>>(b, out);
}